// round 7
// baseline (speedup 1.0000x reference)
#include <cuda_runtime.h>
#include <cuda_fp16.h>
#include <cstdint>
#include <cstddef>

#define HW    9216      // 96*96
#define NCELL (2 * 32 * HW)   // 589824

// Scratch (device globals — allocation-free per harness rules)
__device__ float g_xenc[(size_t)NCELL * 64];       // conv output, channels-last
__device__ float g_A[(size_t)NCELL * 256];         // 30*(xenc @ W1[0:64] + b1)
__device__ __align__(16) __half g_w2h[256 * 264];  // W2^T fp16, [n][k] pad 264
__device__ __align__(16) __half g_w1h[256 * 72];   // W1[0:64]^T hi fp16, [n][k] pad 72
__device__ __align__(16) __half g_w1l[256 * 72];   // W1[0:64]^T lo fp16

// ---------------------------------------------------------------------------
// Helpers
// ---------------------------------------------------------------------------
__device__ __forceinline__ uint32_t smem_u32(const void* p) {
    uint32_t a;
    asm("{ .reg .u64 t; cvta.to.shared.u64 t, %1; cvt.u32.u64 %0, t; }" : "=r"(a) : "l"(p));
    return a;
}
__device__ __forceinline__ void ldsm_x4(uint32_t (&r)[4], uint32_t addr) {
    asm volatile("ldmatrix.sync.aligned.m8n8.x4.shared.b16 {%0,%1,%2,%3}, [%4];"
                 : "=r"(r[0]), "=r"(r[1]), "=r"(r[2]), "=r"(r[3]) : "r"(addr));
}
__device__ __forceinline__ void mma16816(float (&d)[4], const uint32_t (&a)[4],
                                         const uint32_t* b) {
    asm volatile("mma.sync.aligned.m16n8k16.row.col.f32.f16.f16.f32 "
                 "{%0,%1,%2,%3}, {%4,%5,%6,%7}, {%8,%9}, {%0,%1,%2,%3};"
                 : "+f"(d[0]), "+f"(d[1]), "+f"(d[2]), "+f"(d[3])
                 : "r"(a[0]), "r"(a[1]), "r"(a[2]), "r"(a[3]), "r"(b[0]), "r"(b[1]));
}

// ---------------------------------------------------------------------------
// Kernel 1: 3D conv (2 -> 64 channels, 3x3x3, SAME), output channels-last.
// ---------------------------------------------------------------------------
__global__ __launch_bounds__(256) void conv_kernel(
    const float* __restrict__ xr, const float* __restrict__ xi,
    const float* __restrict__ ew, const float* __restrict__ eb)
{
    extern __shared__ float sm[];
    float* ws   = sm;            // 3456
    float* bs   = ws + 3456;     // 64
    float* tile = bs + 64;       // 256 * 65

    int tid = threadIdx.x;
    for (int e = tid; e < 3456; e += 256) ws[e] = ew[e];
    if (tid < 64) bs[tid] = eb[tid];

    int blk = blockIdx.x;
    int bt  = blk / 36;
    int t36 = blk % 36;
    int t   = bt & 31;
    int b   = bt >> 5;
    int pix = t36 * 256 + tid;
    int h   = pix / 96;
    int w   = pix % 96;

    float v[54];
    {
        int e = 0;
        #pragma unroll
        for (int ch = 0; ch < 2; ch++) {
            const float* src = (ch == 0) ? xr : xi;
            #pragma unroll
            for (int dt = -1; dt <= 1; dt++) {
                int  tt  = t + dt;
                bool okt = (tt >= 0) && (tt < 32);
                #pragma unroll
                for (int dh = -1; dh <= 1; dh++) {
                    int  hh  = h + dh;
                    bool okh = okt && (hh >= 0) && (hh < 96);
                    #pragma unroll
                    for (int dw = -1; dw <= 1; dw++) {
                        int  ww = w + dw;
                        bool ok = okh && (ww >= 0) && (ww < 96);
                        v[e++] = ok ? src[(((size_t)(b * 32 + tt)) * 96 + hh) * 96 + ww] : 0.0f;
                    }
                }
            }
        }
    }
    __syncthreads();

    #pragma unroll 4
    for (int c = 0; c < 64; c++) {
        float acc = bs[c];
        #pragma unroll
        for (int q = 0; q < 54; q++) acc = fmaf(v[q], ws[c * 54 + q], acc);
        tile[tid * 65 + c] = acc;
    }
    __syncthreads();

    size_t outbase = ((size_t)bt * HW + (size_t)t36 * 256) * 64;
    for (int e = tid; e < 256 * 64; e += 256) {
        int p = e >> 6, c = e & 63;
        g_xenc[outbase + e] = tile[p * 65 + c];
    }
}

// ---------------------------------------------------------------------------
// Prep kernels: transpose weights into fp16 [n][k] padded layouts
// ---------------------------------------------------------------------------
__global__ void prep_w2(const float* __restrict__ W2)
{
    int idx = blockIdx.x * 256 + threadIdx.x;   // 65536
    int n = idx >> 8, k = idx & 255;
    g_w2h[n * 264 + k] = __float2half_rn(W2[k * 256 + n]);
}
__global__ void prep_w1(const float* __restrict__ W1)
{
    int n = blockIdx.x, k = threadIdx.x;        // 256 x 72
    float v = (k < 64) ? W1[k * 256 + n] : 0.0f;
    __half hi = __float2half_rn(v);
    g_w1h[n * 72 + k] = hi;
    g_w1l[n * 72 + k] = __float2half_rn(v - __half2float(hi));
}

// ---------------------------------------------------------------------------
// Kernel 2 (HMMA, persistent, 512 thr): A = 30 * (xenc @ W1[0:64,:] + b1)
// Per tile: 64 cells x 256 outs, K=64, 3-split fp16 (xh*Wh + xl*Wh + xh*Wl).
// Warp tile 16x64: 4 m-groups x 4 n-groups.
// ---------------------------------------------------------------------------
#define PROW 144              // bytes per [.,72-half] row
#define SMP_WH 0              // 256*144 = 36864
#define SMP_WL 36864
#define SMP_XH 73728          // 64*144 = 9216
#define SMP_XL 82944
#define SMP_TOT 92160

__global__ __launch_bounds__(512, 1) void proj_kernel(
    const float* __restrict__ b1)
{
    extern __shared__ char smem[];
    const uint32_t sb = smem_u32(smem);
    int tid  = threadIdx.x;
    int w    = tid >> 5;
    int lane = tid & 31;

    // Stage W1 hi/lo (resident)
    {
        const float4* s0 = (const float4*)g_w1h;
        const float4* s1 = (const float4*)g_w1l;
        float4* d0 = (float4*)(smem + SMP_WH);
        float4* d1 = (float4*)(smem + SMP_WL);
        for (int i = tid; i < 256 * 144 / 16; i += 512) { d0[i] = s0[i]; d1[i] = s1[i]; }
    }

    const int wm = (w & 3) * 16;       // 4 m-groups x 16 rows
    const int wn = (w >> 2) * 64;      // 4 n-groups x 64 cols

    float b1r[16];
    #pragma unroll
    for (int q = 0; q < 16; q++)
        b1r[q] = b1[wn + (q >> 1) * 8 + (lane & 3) * 2 + (q & 1)];

    const uint32_t a_toff = (uint32_t)(wm + (lane & 15)) * PROW + (uint32_t)(lane >> 4) * 16;
    const uint32_t b_toff = (uint32_t)(wn + (lane & 7) + ((lane >> 4) & 1) * 8) * PROW
                          + (uint32_t)((lane >> 3) & 1) * 16;

    const int lrow = tid >> 3;             // cell row this thread loads (64 rows)
    const int lk   = (tid & 7) * 8;        // 8 k values
    __syncthreads();

    for (int tile = blockIdx.x; tile < 9216; tile += 148) {
        size_t cell0 = (size_t)tile * 64;

        // Load + split xenc into smem (batched loads first)
        {
            const float4* src = (const float4*)(g_xenc + (cell0 + lrow) * 64 + lk);
            float4 v0 = src[0], v1 = src[1];
            float vv[8] = {v0.x, v0.y, v0.z, v0.w, v1.x, v1.y, v1.z, v1.w};
            uint32_t hv[4], lv[4];
            #pragma unroll
            for (int p = 0; p < 4; p++) {
                __half h0 = __float2half_rn(vv[2*p]),   h1 = __float2half_rn(vv[2*p+1]);
                __half l0 = __float2half_rn(vv[2*p]   - __half2float(h0));
                __half l1 = __float2half_rn(vv[2*p+1] - __half2float(h1));
                __half2 ph = __halves2half2(h0, h1), pl = __halves2half2(l0, l1);
                hv[p] = *(uint32_t*)&ph;  lv[p] = *(uint32_t*)&pl;
            }
            *(uint4*)(smem + SMP_XH + lrow * PROW + lk * 2) = make_uint4(hv[0], hv[1], hv[2], hv[3]);
            *(uint4*)(smem + SMP_XL + lrow * PROW + lk * 2) = make_uint4(lv[0], lv[1], lv[2], lv[3]);
        }
        __syncthreads();

        float acc[8][4];
        #pragma unroll
        for (int nt = 0; nt < 8; nt++)
            #pragma unroll
            for (int c = 0; c < 4; c++) acc[nt][c] = 0.0f;

        const uint32_t abase[3] = {sb + SMP_XH, sb + SMP_XL, sb + SMP_XH};
        const uint32_t bbase[3] = {sb + SMP_WH, sb + SMP_WH, sb + SMP_WL};
        #pragma unroll
        for (int s = 0; s < 3; s++) {
            uint32_t a_addr = abase[s] + a_toff;
            uint32_t b_addr = bbase[s] + b_toff;
            #pragma unroll
            for (int ks = 0; ks < 4; ks++) {
                uint32_t af[4];
                ldsm_x4(af, a_addr);
                #pragma unroll
                for (int np = 0; np < 4; np++) {
                    uint32_t bf[4];
                    ldsm_x4(bf, b_addr + np * 16 * PROW);
                    mma16816(acc[np * 2 + 0], af, bf + 0);
                    mma16816(acc[np * 2 + 1], af, bf + 2);
                }
                a_addr += 32;
                b_addr += 32;
            }
        }

        // Epilogue: A = 30*(z1 + b1), direct STG.64
        {
            int r0 = wm + (lane >> 2);
            #pragma unroll
            for (int nt = 0; nt < 8; nt++) {
                int n0 = wn + nt * 8 + (lane & 3) * 2;
                float2 v0, v1;
                v0.x = 30.0f * (acc[nt][0] + b1r[nt*2+0]);
                v0.y = 30.0f * (acc[nt][1] + b1r[nt*2+1]);
                v1.x = 30.0f * (acc[nt][2] + b1r[nt*2+0]);
                v1.y = 30.0f * (acc[nt][3] + b1r[nt*2+1]);
                *(float2*)&g_A[(cell0 + r0)     * 256 + n0] = v0;
                *(float2*)&g_A[(cell0 + r0 + 8) * 256 + n0] = v1;
            }
        }
        __syncthreads();
    }
}

// ---------------------------------------------------------------------------
// Kernel 3: persistent HMMA SIREN (512 thr), single-fp16 A, double-buffered,
// batched phase-1 loads. Warp tile 16x64: 4 m-groups x 4 n-groups.
// ---------------------------------------------------------------------------
#define AROW   528            // bytes per [.,264-half] row
#define SM_B    0             // 256*528 = 135168
#define SM_A0   135168        // 64*528  =  33792
#define SM_A1   168960        // 64*528  =  33792
#define SM_W1T  202752        // 1024
#define SM_SLOT 203776        // 512*4 = 2048
#define SM_TOT  205824

__global__ __launch_bounds__(512, 1) void main_kernel(
    const float* __restrict__ tcoord, const float* __restrict__ W1,
    const float* __restrict__ b2, const float* __restrict__ W3,
    const float* __restrict__ b3, float* __restrict__ out)
{
    extern __shared__ char smem[];
    const uint32_t sb = smem_u32(smem);
    int tid  = threadIdx.x;
    int w    = tid >> 5;
    int lane = tid & 31;

    // Stage W2 fp16 (resident) + w1 last row
    {
        const float4* src = (const float4*)g_w2h;
        float4*       dst = (float4*)(smem + SM_B);
        for (int i = tid; i < 256 * 528 / 16; i += 512) dst[i] = src[i];
    }
    float* w1t   = (float*)(smem + SM_W1T);
    float* slots = (float*)(smem + SM_SLOT);
    if (tid < 256) w1t[tid] = W1[64 * 256 + tid];
    __syncthreads();

    const float b3v = b3[0];

    const int wm = (w & 3) * 16;       // 4 m-groups x 16 rows
    const int wn = (w >> 2) * 64;      // 4 n-groups x 64 cols
    const int ng = w >> 2;

    float b2r[16], w3r[16];
    #pragma unroll
    for (int q = 0; q < 16; q++) {
        int n = wn + (q >> 1) * 8 + (lane & 3) * 2 + (q & 1);
        b2r[q] = 30.0f * b2[n];
        w3r[q] = W3[n];
    }

    const uint32_t a_toff = (uint32_t)(wm + (lane & 15)) * AROW + (uint32_t)(lane >> 4) * 16;
    const uint32_t b_toff = (uint32_t)(wn + (lane & 7) + ((lane >> 4) & 1) * 8) * AROW
                          + (uint32_t)((lane >> 3) & 1) * 16;
    const uint32_t b_base = sb + SM_B + b_toff;

    const int p1row = tid >> 3;          // phase-1 row (64 rows, 8 thr/row)
    const int p1k   = (tid & 7) * 32;    // phase-1 k start (32 values)

    for (int tile = blockIdx.x; tile < 9216; tile += 148) {
        int bq = tile & 63, pt = tile >> 6;
        int b  = bq >> 5,  pix0 = pt * 64;

        float tc = tcoord[bq];
        tc = fminf(fmaxf(tc, -1.0f), 1.0f - 1e-6f);
        const float df = 2.0f / 31.0f;
        int   ti  = (int)floorf((tc + 1.0f) / df);
        float tau = (tc - (-1.0f + (float)ti * df)) / df;
        float ctc = 30.0f * tc;

        #pragma unroll 1
        for (int h = 0; h < 2; h++) {
            // ---- Phase 1: batched LDG of A, then sin -> fp16 -> smem ----
            {
                const float4* s4 = (const float4*)(
                    g_A + ((size_t)(b * 32 + ti + h) * HW + pix0 + p1row) * 256 + p1k);
                float4 a4[8];
                #pragma unroll
                for (int j = 0; j < 8; j++) a4[j] = s4[j];   // MLP=8 front-batched

                char* hb = smem + (h ? SM_A1 : SM_A0) + p1row * AROW + p1k * 2;
                #pragma unroll
                for (int j = 0; j < 4; j++) {
                    float4 a0 = a4[2*j], a1 = a4[2*j+1];
                    const float4 w0  = *(const float4*)&w1t[p1k + 8*j];
                    const float4 w1v = *(const float4*)&w1t[p1k + 8*j + 4];
                    float s[8];
                    s[0] = __sinf(fmaf(ctc, w0.x,  a0.x));
                    s[1] = __sinf(fmaf(ctc, w0.y,  a0.y));
                    s[2] = __sinf(fmaf(ctc, w0.z,  a0.z));
                    s[3] = __sinf(fmaf(ctc, w0.w,  a0.w));
                    s[4] = __sinf(fmaf(ctc, w1v.x, a1.x));
                    s[5] = __sinf(fmaf(ctc, w1v.y, a1.y));
                    s[6] = __sinf(fmaf(ctc, w1v.z, a1.z));
                    s[7] = __sinf(fmaf(ctc, w1v.w, a1.w));
                    uint32_t hv[4];
                    #pragma unroll
                    for (int p = 0; p < 4; p++) {
                        __half2 ph = __halves2half2(__float2half_rn(s[2*p]),
                                                    __float2half_rn(s[2*p+1]));
                        hv[p] = *(uint32_t*)&ph;
                    }
                    *(uint4*)(hb + j * 16) = make_uint4(hv[0], hv[1], hv[2], hv[3]);
                }
            }
            __syncthreads();

            // ---- GEMM: acc = h1 @ W2 ----
            float acc[8][4];
            #pragma unroll
            for (int nt = 0; nt < 8; nt++)
                #pragma unroll
                for (int c = 0; c < 4; c++) acc[nt][c] = 0.0f;

            uint32_t a_addr = sb + (h ? SM_A1 : SM_A0) + a_toff;
            uint32_t b_addr = b_base;
            #pragma unroll 4
            for (int ks = 0; ks < 16; ks++) {
                uint32_t af[4];
                ldsm_x4(af, a_addr);
                #pragma unroll
                for (int np = 0; np < 4; np++) {
                    uint32_t bf[4];
                    ldsm_x4(bf, b_addr + np * 16 * AROW);
                    mma16816(acc[np * 2 + 0], af, bf + 0);
                    mma16816(acc[np * 2 + 1], af, bf + 2);
                }
                a_addr += 32;
                b_addr += 32;
            }

            // ---- Epilogue: sin(30*z2 + 30*b2) . W3, reduce ----
            float p[2];
            #pragma unroll
            for (int rh = 0; rh < 2; rh++) {
                float s = 0.0f;
                #pragma unroll
                for (int nt = 0; nt < 8; nt++) {
                    int c0 = rh * 2;
                    s = fmaf(__sinf(fmaf(30.0f, acc[nt][c0],     b2r[nt*2+0])), w3r[nt*2+0], s);
                    s = fmaf(__sinf(fmaf(30.0f, acc[nt][c0 + 1], b2r[nt*2+1])), w3r[nt*2+1], s);
                }
                p[rh] = s;
            }
            #pragma unroll
            for (int msk = 1; msk < 4; msk <<= 1) {
                #pragma unroll
                for (int rh = 0; rh < 2; rh++)
                    p[rh] += __shfl_xor_sync(0xffffffffu, p[rh], msk);
            }
            if ((lane & 3) == 0) {
                #pragma unroll
                for (int rh = 0; rh < 2; rh++)
                    slots[h * 256 + ng * 64 + wm + rh * 8 + (lane >> 2)] = p[rh];
            }
        }
        __syncthreads();

        if (tid < 64) {
            float zf = slots[tid]       + slots[64 + tid]  + slots[128 + tid] + slots[192 + tid];
            float zc = slots[256 + tid] + slots[320 + tid] + slots[384 + tid] + slots[448 + tid];
            out[(size_t)bq * HW + pix0 + tid] = fmaf(tau, zc - zf, zf) + b3v;
        }
        __syncthreads();
    }
}

// ---------------------------------------------------------------------------
extern "C" void kernel_launch(void* const* d_in, const int* in_sizes, int n_in,
                              void* d_out, int out_size)
{
    const float* x_real  = (const float*)d_in[0];
    const float* x_imag  = (const float*)d_in[1];
    const float* t_coord = (const float*)d_in[2];
    const float* enc_w   = (const float*)d_in[3];
    const float* enc_b   = (const float*)d_in[4];
    const float* W1      = (const float*)d_in[5];
    const float* b1      = (const float*)d_in[6];
    const float* W2      = (const float*)d_in[7];
    const float* b2      = (const float*)d_in[8];
    const float* W3      = (const float*)d_in[9];
    const float* b3      = (const float*)d_in[10];
    float*       out     = (float*)d_out;

    size_t smem1 = (3456 + 64 + 256 * 65) * sizeof(float);
    cudaFuncSetAttribute(conv_kernel, cudaFuncAttributeMaxDynamicSharedMemorySize, (int)smem1);
    cudaFuncSetAttribute(proj_kernel, cudaFuncAttributeMaxDynamicSharedMemorySize, SMP_TOT);
    cudaFuncSetAttribute(main_kernel, cudaFuncAttributeMaxDynamicSharedMemorySize, SM_TOT);

    prep_w2<<<256, 256>>>(W2);
    prep_w1<<<256, 72>>>(W1);
    conv_kernel<<<2304, 256, smem1>>>(x_real, x_imag, enc_w, enc_b);
    proj_kernel<<<148, 512, SMP_TOT>>>(b1);
    main_kernel<<<148, 512, SM_TOT>>>(t_coord, W1, b2, W3, b3, out);
}

// round 8
// speedup vs baseline: 1.1541x; 1.1541x over previous
#include <cuda_runtime.h>
#include <cuda_fp16.h>
#include <cstdint>
#include <cstddef>

#define HW    9216      // 96*96
#define NCELL (2 * 32 * HW)   // 589824

// Scratch (device globals — allocation-free per harness rules)
__device__ float g_xenc[(size_t)NCELL * 64];       // conv output, channels-last
__device__ float g_A[(size_t)NCELL * 256];         // 30*(xenc @ W1[0:64] + b1)
__device__ __align__(16) __half g_w2h[256 * 264];  // W2^T fp16, [n][k] pad 264
__device__ __align__(16) __half g_w1h[256 * 72];   // W1[0:64]^T hi fp16, [n][k] pad 72
__device__ __align__(16) __half g_w1l[256 * 72];   // W1[0:64]^T lo fp16

// ---------------------------------------------------------------------------
// Helpers
// ---------------------------------------------------------------------------
__device__ __forceinline__ uint32_t smem_u32(const void* p) {
    uint32_t a;
    asm("{ .reg .u64 t; cvta.to.shared.u64 t, %1; cvt.u32.u64 %0, t; }" : "=r"(a) : "l"(p));
    return a;
}
__device__ __forceinline__ void ldsm_x4(uint32_t (&r)[4], uint32_t addr) {
    asm volatile("ldmatrix.sync.aligned.m8n8.x4.shared.b16 {%0,%1,%2,%3}, [%4];"
                 : "=r"(r[0]), "=r"(r[1]), "=r"(r[2]), "=r"(r[3]) : "r"(addr));
}
__device__ __forceinline__ void mma16816(float (&d)[4], const uint32_t (&a)[4],
                                         const uint32_t* b) {
    asm volatile("mma.sync.aligned.m16n8k16.row.col.f32.f16.f16.f32 "
                 "{%0,%1,%2,%3}, {%4,%5,%6,%7}, {%8,%9}, {%0,%1,%2,%3};"
                 : "+f"(d[0]), "+f"(d[1]), "+f"(d[2]), "+f"(d[3])
                 : "r"(a[0]), "r"(a[1]), "r"(a[2]), "r"(a[3]), "r"(b[0]), "r"(b[1]));
}

// ---------------------------------------------------------------------------
// Kernel 1: 3D conv (2 -> 64 channels, 3x3x3, SAME), output channels-last.
// ---------------------------------------------------------------------------
__global__ __launch_bounds__(256) void conv_kernel(
    const float* __restrict__ xr, const float* __restrict__ xi,
    const float* __restrict__ ew, const float* __restrict__ eb)
{
    extern __shared__ float sm[];
    float* ws   = sm;            // 3456
    float* bs   = ws + 3456;     // 64
    float* tile = bs + 64;       // 256 * 65

    int tid = threadIdx.x;
    for (int e = tid; e < 3456; e += 256) ws[e] = ew[e];
    if (tid < 64) bs[tid] = eb[tid];

    int blk = blockIdx.x;
    int bt  = blk / 36;
    int t36 = blk % 36;
    int t   = bt & 31;
    int b   = bt >> 5;
    int pix = t36 * 256 + tid;
    int h   = pix / 96;
    int w   = pix % 96;

    float v[54];
    {
        int e = 0;
        #pragma unroll
        for (int ch = 0; ch < 2; ch++) {
            const float* src = (ch == 0) ? xr : xi;
            #pragma unroll
            for (int dt = -1; dt <= 1; dt++) {
                int  tt  = t + dt;
                bool okt = (tt >= 0) && (tt < 32);
                #pragma unroll
                for (int dh = -1; dh <= 1; dh++) {
                    int  hh  = h + dh;
                    bool okh = okt && (hh >= 0) && (hh < 96);
                    #pragma unroll
                    for (int dw = -1; dw <= 1; dw++) {
                        int  ww = w + dw;
                        bool ok = okh && (ww >= 0) && (ww < 96);
                        v[e++] = ok ? src[(((size_t)(b * 32 + tt)) * 96 + hh) * 96 + ww] : 0.0f;
                    }
                }
            }
        }
    }
    __syncthreads();

    #pragma unroll 4
    for (int c = 0; c < 64; c++) {
        float acc = bs[c];
        #pragma unroll
        for (int q = 0; q < 54; q++) acc = fmaf(v[q], ws[c * 54 + q], acc);
        tile[tid * 65 + c] = acc;
    }
    __syncthreads();

    size_t outbase = ((size_t)bt * HW + (size_t)t36 * 256) * 64;
    for (int e = tid; e < 256 * 64; e += 256) {
        int p = e >> 6, c = e & 63;
        g_xenc[outbase + e] = tile[p * 65 + c];
    }
}

// ---------------------------------------------------------------------------
// Prep kernels: transpose weights into fp16 [n][k] padded layouts
// ---------------------------------------------------------------------------
__global__ void prep_w2(const float* __restrict__ W2)
{
    int idx = blockIdx.x * 256 + threadIdx.x;   // 65536
    int n = idx >> 8, k = idx & 255;
    g_w2h[n * 264 + k] = __float2half_rn(W2[k * 256 + n]);
}
__global__ void prep_w1(const float* __restrict__ W1)
{
    int n = blockIdx.x, k = threadIdx.x;        // 256 x 72
    float v = (k < 64) ? W1[k * 256 + n] : 0.0f;
    __half hi = __float2half_rn(v);
    g_w1h[n * 72 + k] = hi;
    g_w1l[n * 72 + k] = __float2half_rn(v - __half2float(hi));
}

// ---------------------------------------------------------------------------
// Kernel 2 (HMMA, persistent, 512 thr): A = 30 * (xenc @ W1[0:64,:] + b1)
// ---------------------------------------------------------------------------
#define PROW 144              // bytes per [.,72-half] row
#define SMP_WH 0              // 256*144 = 36864
#define SMP_WL 36864
#define SMP_XH 73728          // 64*144 = 9216
#define SMP_XL 82944
#define SMP_TOT 92160

__global__ __launch_bounds__(512, 1) void proj_kernel(
    const float* __restrict__ b1)
{
    extern __shared__ char smem[];
    const uint32_t sb = smem_u32(smem);
    int tid  = threadIdx.x;
    int w    = tid >> 5;
    int lane = tid & 31;

    // Stage W1 hi/lo (resident)
    {
        const float4* s0 = (const float4*)g_w1h;
        const float4* s1 = (const float4*)g_w1l;
        float4* d0 = (float4*)(smem + SMP_WH);
        float4* d1 = (float4*)(smem + SMP_WL);
        for (int i = tid; i < 256 * 144 / 16; i += 512) { d0[i] = s0[i]; d1[i] = s1[i]; }
    }

    const int wm = (w & 3) * 16;       // 4 m-groups x 16 rows
    const int wn = (w >> 2) * 64;      // 4 n-groups x 64 cols

    float b1r[16];
    #pragma unroll
    for (int q = 0; q < 16; q++)
        b1r[q] = b1[wn + (q >> 1) * 8 + (lane & 3) * 2 + (q & 1)];

    const uint32_t a_toff = (uint32_t)(wm + (lane & 15)) * PROW + (uint32_t)(lane >> 4) * 16;
    const uint32_t b_toff = (uint32_t)(wn + (lane & 7) + ((lane >> 4) & 1) * 8) * PROW
                          + (uint32_t)((lane >> 3) & 1) * 16;

    const int lrow = tid >> 3;             // cell row this thread loads (64 rows)
    const int lk   = (tid & 7) * 8;        // 8 k values
    __syncthreads();

    for (int tile = blockIdx.x; tile < 9216; tile += 148) {
        size_t cell0 = (size_t)tile * 64;

        // Load + split xenc into smem (batched loads first)
        {
            const float4* src = (const float4*)(g_xenc + (cell0 + lrow) * 64 + lk);
            float4 v0 = src[0], v1 = src[1];
            float vv[8] = {v0.x, v0.y, v0.z, v0.w, v1.x, v1.y, v1.z, v1.w};
            uint32_t hv[4], lv[4];
            #pragma unroll
            for (int p = 0; p < 4; p++) {
                __half h0 = __float2half_rn(vv[2*p]),   h1 = __float2half_rn(vv[2*p+1]);
                __half l0 = __float2half_rn(vv[2*p]   - __half2float(h0));
                __half l1 = __float2half_rn(vv[2*p+1] - __half2float(h1));
                __half2 ph = __halves2half2(h0, h1), pl = __halves2half2(l0, l1);
                hv[p] = *(uint32_t*)&ph;  lv[p] = *(uint32_t*)&pl;
            }
            *(uint4*)(smem + SMP_XH + lrow * PROW + lk * 2) = make_uint4(hv[0], hv[1], hv[2], hv[3]);
            *(uint4*)(smem + SMP_XL + lrow * PROW + lk * 2) = make_uint4(lv[0], lv[1], lv[2], lv[3]);
        }
        __syncthreads();

        float acc[8][4];
        #pragma unroll
        for (int nt = 0; nt < 8; nt++)
            #pragma unroll
            for (int c = 0; c < 4; c++) acc[nt][c] = 0.0f;

        const uint32_t abase[3] = {sb + SMP_XH, sb + SMP_XL, sb + SMP_XH};
        const uint32_t bbase[3] = {sb + SMP_WH, sb + SMP_WH, sb + SMP_WL};
        #pragma unroll
        for (int s = 0; s < 3; s++) {
            uint32_t a_addr = abase[s] + a_toff;
            uint32_t b_addr = bbase[s] + b_toff;
            #pragma unroll
            for (int ks = 0; ks < 4; ks++) {
                uint32_t af[4];
                ldsm_x4(af, a_addr);
                #pragma unroll
                for (int np = 0; np < 4; np++) {
                    uint32_t bf[4];
                    ldsm_x4(bf, b_addr + np * 16 * PROW);
                    mma16816(acc[np * 2 + 0], af, bf + 0);
                    mma16816(acc[np * 2 + 1], af, bf + 2);
                }
                a_addr += 32;
                b_addr += 32;
            }
        }

        // Epilogue: A = 30*(z1 + b1), direct STG.64
        {
            int r0 = wm + (lane >> 2);
            #pragma unroll
            for (int nt = 0; nt < 8; nt++) {
                int n0 = wn + nt * 8 + (lane & 3) * 2;
                float2 v0, v1;
                v0.x = 30.0f * (acc[nt][0] + b1r[nt*2+0]);
                v0.y = 30.0f * (acc[nt][1] + b1r[nt*2+1]);
                v1.x = 30.0f * (acc[nt][2] + b1r[nt*2+0]);
                v1.y = 30.0f * (acc[nt][3] + b1r[nt*2+1]);
                *(float2*)&g_A[(cell0 + r0)     * 256 + n0] = v0;
                *(float2*)&g_A[(cell0 + r0 + 8) * 256 + n0] = v1;
            }
        }
        __syncthreads();
    }
}

// ---------------------------------------------------------------------------
// Kernel 3: persistent HMMA SIREN (256 thr, warp tile 32x64 — MMA-bound ratio).
// Both halves' phase-1 before ONE barrier; GEMM h0 -> epi h0 -> GEMM h1 ->
// epi h1 barrier-free (disjoint slot regions) so MUFU overlaps MMA via drift.
// ---------------------------------------------------------------------------
#define AROW   528            // bytes per [.,264-half] row
#define SM_B    0             // 256*528 = 135168
#define SM_A0   135168        // 64*528  =  33792
#define SM_A1   168960        // 64*528  =  33792
#define SM_W1T  202752        // 1024
#define SM_SLOT 203776        // 512*4 = 2048
#define SM_TOT  205824

__global__ __launch_bounds__(256, 1) void main_kernel(
    const float* __restrict__ tcoord, const float* __restrict__ W1,
    const float* __restrict__ b2, const float* __restrict__ W3,
    const float* __restrict__ b3, float* __restrict__ out)
{
    extern __shared__ char smem[];
    const uint32_t sb = smem_u32(smem);
    int tid  = threadIdx.x;
    int w    = tid >> 5;
    int lane = tid & 31;

    // Stage W2 fp16 (resident) + w1 last row
    {
        const float4* src = (const float4*)g_w2h;
        float4*       dst = (float4*)(smem + SM_B);
        for (int i = tid; i < 256 * 528 / 16; i += 256) dst[i] = src[i];
    }
    float* w1t   = (float*)(smem + SM_W1T);
    float* slots = (float*)(smem + SM_SLOT);
    if (tid < 256) w1t[tid] = W1[64 * 256 + tid];
    __syncthreads();

    const float b3v = b3[0];

    const int wm = (w & 1) * 32;       // 2 m-groups x 32 rows
    const int wn = (w >> 1) * 64;      // 4 n-groups x 64 cols
    const int ng = w >> 1;

    float b2r[16], w3r[16];
    #pragma unroll
    for (int q = 0; q < 16; q++) {
        int n = wn + (q >> 1) * 8 + (lane & 3) * 2 + (q & 1);
        b2r[q] = 30.0f * b2[n];
        w3r[q] = W3[n];
    }

    const uint32_t a_toff = (uint32_t)(wm + (lane & 15)) * AROW + (uint32_t)(lane >> 4) * 16;
    const uint32_t b_toff = (uint32_t)(wn + (lane & 7) + ((lane >> 4) & 1) * 8) * AROW
                          + (uint32_t)((lane >> 3) & 1) * 16;
    const uint32_t b_base = sb + SM_B + b_toff;

    const int p1row = tid >> 2;          // phase-1 row (64 rows, 4 thr/row)
    const int p1k   = (tid & 3) * 64;    // phase-1 k start (64 values)

    for (int tile = blockIdx.x; tile < 9216; tile += 148) {
        int bq = tile & 63, pt = tile >> 6;
        int b  = bq >> 5,  pix0 = pt * 64;

        float tc = tcoord[bq];
        tc = fminf(fmaxf(tc, -1.0f), 1.0f - 1e-6f);
        const float df = 2.0f / 31.0f;
        int   ti  = (int)floorf((tc + 1.0f) / df);
        float tau = (tc - (-1.0f + (float)ti * df)) / df;
        float ctc = 30.0f * tc;

        // ---- Phase 1 (both halves): batched LDG, sin -> fp16 -> smem ----
        #pragma unroll 1
        for (int h = 0; h < 2; h++) {
            const float4* s4 = (const float4*)(
                g_A + ((size_t)(b * 32 + ti + h) * HW + pix0 + p1row) * 256 + p1k);
            float4 a4[16];
            #pragma unroll
            for (int j = 0; j < 16; j++) a4[j] = s4[j];   // MLP=16 front-batched

            char* hb = smem + (h ? SM_A1 : SM_A0) + p1row * AROW + p1k * 2;
            #pragma unroll
            for (int j = 0; j < 8; j++) {
                float4 a0 = a4[2*j], a1 = a4[2*j+1];
                const float4 w0  = *(const float4*)&w1t[p1k + 8*j];
                const float4 w1v = *(const float4*)&w1t[p1k + 8*j + 4];
                float s[8];
                s[0] = __sinf(fmaf(ctc, w0.x,  a0.x));
                s[1] = __sinf(fmaf(ctc, w0.y,  a0.y));
                s[2] = __sinf(fmaf(ctc, w0.z,  a0.z));
                s[3] = __sinf(fmaf(ctc, w0.w,  a0.w));
                s[4] = __sinf(fmaf(ctc, w1v.x, a1.x));
                s[5] = __sinf(fmaf(ctc, w1v.y, a1.y));
                s[6] = __sinf(fmaf(ctc, w1v.z, a1.z));
                s[7] = __sinf(fmaf(ctc, w1v.w, a1.w));
                uint32_t hv[4];
                #pragma unroll
                for (int p = 0; p < 4; p++) {
                    __half2 ph = __halves2half2(__float2half_rn(s[2*p]),
                                                __float2half_rn(s[2*p+1]));
                    hv[p] = *(uint32_t*)&ph;
                }
                *(uint4*)(hb + j * 16) = make_uint4(hv[0], hv[1], hv[2], hv[3]);
            }
        }
        __syncthreads();   // single barrier covering both A buffers

        // ---- GEMM + epilogue per half, no barriers (warps drift) ----
        #pragma unroll 1
        for (int h = 0; h < 2; h++) {
            float acc[2][8][4];
            #pragma unroll
            for (int mt = 0; mt < 2; mt++)
                #pragma unroll
                for (int nt = 0; nt < 8; nt++)
                    #pragma unroll
                    for (int c = 0; c < 4; c++) acc[mt][nt][c] = 0.0f;

            uint32_t a_addr = sb + (h ? SM_A1 : SM_A0) + a_toff;
            uint32_t b_addr = b_base;
            #pragma unroll 4
            for (int ks = 0; ks < 16; ks++) {
                uint32_t af0[4], af1[4];
                ldsm_x4(af0, a_addr);
                ldsm_x4(af1, a_addr + 16 * AROW);
                #pragma unroll
                for (int np = 0; np < 4; np++) {
                    uint32_t bf[4];
                    ldsm_x4(bf, b_addr + np * 16 * AROW);
                    mma16816(acc[0][np * 2 + 0], af0, bf + 0);
                    mma16816(acc[0][np * 2 + 1], af0, bf + 2);
                    mma16816(acc[1][np * 2 + 0], af1, bf + 0);
                    mma16816(acc[1][np * 2 + 1], af1, bf + 2);
                }
                a_addr += 32;
                b_addr += 32;
            }

            // Epilogue: sin(30*z2 + 30*b2) . W3, shuffle-reduce over n-quads
            float p[2][2];
            #pragma unroll
            for (int mt = 0; mt < 2; mt++)
                #pragma unroll
                for (int rh = 0; rh < 2; rh++) {
                    float s = 0.0f;
                    #pragma unroll
                    for (int nt = 0; nt < 8; nt++) {
                        int c0 = rh * 2;
                        s = fmaf(__sinf(fmaf(30.0f, acc[mt][nt][c0],     b2r[nt*2+0])), w3r[nt*2+0], s);
                        s = fmaf(__sinf(fmaf(30.0f, acc[mt][nt][c0 + 1], b2r[nt*2+1])), w3r[nt*2+1], s);
                    }
                    p[mt][rh] = s;
                }
            #pragma unroll
            for (int msk = 1; msk < 4; msk <<= 1) {
                #pragma unroll
                for (int mt = 0; mt < 2; mt++)
                    #pragma unroll
                    for (int rh = 0; rh < 2; rh++)
                        p[mt][rh] += __shfl_xor_sync(0xffffffffu, p[mt][rh], msk);
            }
            if ((lane & 3) == 0) {
                #pragma unroll
                for (int mt = 0; mt < 2; mt++)
                    #pragma unroll
                    for (int rh = 0; rh < 2; rh++)
                        slots[h * 256 + ng * 64 + wm + mt * 16 + rh * 8 + (lane >> 2)] = p[mt][rh];
            }
        }
        __syncthreads();

        if (tid < 64) {
            float zf = slots[tid]       + slots[64 + tid]  + slots[128 + tid] + slots[192 + tid];
            float zc = slots[256 + tid] + slots[320 + tid] + slots[384 + tid] + slots[448 + tid];
            out[(size_t)bq * HW + pix0 + tid] = fmaf(tau, zc - zf, zf) + b3v;
        }
        __syncthreads();
    }
}

// ---------------------------------------------------------------------------
extern "C" void kernel_launch(void* const* d_in, const int* in_sizes, int n_in,
                              void* d_out, int out_size)
{
    const float* x_real  = (const float*)d_in[0];
    const float* x_imag  = (const float*)d_in[1];
    const float* t_coord = (const float*)d_in[2];
    const float* enc_w   = (const float*)d_in[3];
    const float* enc_b   = (const float*)d_in[4];
    const float* W1      = (const float*)d_in[5];
    const float* b1      = (const float*)d_in[6];
    const float* W2      = (const float*)d_in[7];
    const float* b2      = (const float*)d_in[8];
    const float* W3      = (const float*)d_in[9];
    const float* b3      = (const float*)d_in[10];
    float*       out     = (float*)d_out;

    size_t smem1 = (3456 + 64 + 256 * 65) * sizeof(float);
    cudaFuncSetAttribute(conv_kernel, cudaFuncAttributeMaxDynamicSharedMemorySize, (int)smem1);
    cudaFuncSetAttribute(proj_kernel, cudaFuncAttributeMaxDynamicSharedMemorySize, SMP_TOT);
    cudaFuncSetAttribute(main_kernel, cudaFuncAttributeMaxDynamicSharedMemorySize, SM_TOT);

    prep_w2<<<256, 256>>>(W2);
    prep_w1<<<256, 72>>>(W1);
    conv_kernel<<<2304, 256, smem1>>>(x_real, x_imag, enc_w, enc_b);
    proj_kernel<<<148, 512, SMP_TOT>>>(b1);
    main_kernel<<<148, 256, SM_TOT>>>(t_coord, W1, b2, W3, b3, out);
}

// round 10
// speedup vs baseline: 1.2719x; 1.1021x over previous
#include <cuda_runtime.h>
#include <cuda_fp16.h>
#include <cstdint>
#include <cstddef>

#define HW    9216      // 96*96
#define NCELL (2 * 32 * HW)   // 589824

// Scratch (device globals — allocation-free per harness rules)
__device__ float g_xenc[(size_t)NCELL * 64];       // conv output, channels-last
__device__ float g_A[(size_t)NCELL * 256];         // 30*(xenc @ W1[0:64] + b1)
__device__ __align__(16) __half g_w2h[256 * 264];  // W2^T fp16, [n][k] pad 264
__device__ __align__(16) __half g_w1h[256 * 72];   // W1[0:64]^T hi fp16, [n][k] pad 72
__device__ __align__(16) __half g_w1l[256 * 72];   // W1[0:64]^T lo fp16

// ---------------------------------------------------------------------------
// Helpers
// ---------------------------------------------------------------------------
__device__ __forceinline__ uint32_t smem_u32(const void* p) {
    uint32_t a;
    asm("{ .reg .u64 t; cvta.to.shared.u64 t, %1; cvt.u32.u64 %0, t; }" : "=r"(a) : "l"(p));
    return a;
}
__device__ __forceinline__ void ldsm_x4(uint32_t (&r)[4], uint32_t addr) {
    asm volatile("ldmatrix.sync.aligned.m8n8.x4.shared.b16 {%0,%1,%2,%3}, [%4];"
                 : "=r"(r[0]), "=r"(r[1]), "=r"(r[2]), "=r"(r[3]) : "r"(addr));
}
__device__ __forceinline__ void mma16816(float (&d)[4], const uint32_t (&a)[4],
                                         const uint32_t* b) {
    asm volatile("mma.sync.aligned.m16n8k16.row.col.f32.f16.f16.f32 "
                 "{%0,%1,%2,%3}, {%4,%5,%6,%7}, {%8,%9}, {%0,%1,%2,%3};"
                 : "+f"(d[0]), "+f"(d[1]), "+f"(d[2]), "+f"(d[3])
                 : "r"(a[0]), "r"(a[1]), "r"(a[2]), "r"(a[3]), "r"(b[0]), "r"(b[1]));
}

// ---------------------------------------------------------------------------
// Kernel 1: 3D conv (2 -> 64 channels, 3x3x3, SAME), output channels-last.
// ---------------------------------------------------------------------------
__global__ __launch_bounds__(256) void conv_kernel(
    const float* __restrict__ xr, const float* __restrict__ xi,
    const float* __restrict__ ew, const float* __restrict__ eb)
{
    extern __shared__ float sm[];
    float* ws   = sm;            // 3456
    float* bs   = ws + 3456;     // 64
    float* tile = bs + 64;       // 256 * 65

    int tid = threadIdx.x;
    for (int e = tid; e < 3456; e += 256) ws[e] = ew[e];
    if (tid < 64) bs[tid] = eb[tid];

    int blk = blockIdx.x;
    int bt  = blk / 36;
    int t36 = blk % 36;
    int t   = bt & 31;
    int b   = bt >> 5;
    int pix = t36 * 256 + tid;
    int h   = pix / 96;
    int w   = pix % 96;

    float v[54];
    {
        int e = 0;
        #pragma unroll
        for (int ch = 0; ch < 2; ch++) {
            const float* src = (ch == 0) ? xr : xi;
            #pragma unroll
            for (int dt = -1; dt <= 1; dt++) {
                int  tt  = t + dt;
                bool okt = (tt >= 0) && (tt < 32);
                #pragma unroll
                for (int dh = -1; dh <= 1; dh++) {
                    int  hh  = h + dh;
                    bool okh = okt && (hh >= 0) && (hh < 96);
                    #pragma unroll
                    for (int dw = -1; dw <= 1; dw++) {
                        int  ww = w + dw;
                        bool ok = okh && (ww >= 0) && (ww < 96);
                        v[e++] = ok ? src[(((size_t)(b * 32 + tt)) * 96 + hh) * 96 + ww] : 0.0f;
                    }
                }
            }
        }
    }
    __syncthreads();

    #pragma unroll 4
    for (int c = 0; c < 64; c++) {
        float acc = bs[c];
        #pragma unroll
        for (int q = 0; q < 54; q++) acc = fmaf(v[q], ws[c * 54 + q], acc);
        tile[tid * 65 + c] = acc;
    }
    __syncthreads();

    size_t outbase = ((size_t)bt * HW + (size_t)t36 * 256) * 64;
    for (int e = tid; e < 256 * 64; e += 256) {
        int p = e >> 6, c = e & 63;
        g_xenc[outbase + e] = tile[p * 65 + c];
    }
}

// ---------------------------------------------------------------------------
// Prep kernels: transpose weights into fp16 [n][k] padded layouts
// ---------------------------------------------------------------------------
__global__ void prep_w2(const float* __restrict__ W2)
{
    int idx = blockIdx.x * 256 + threadIdx.x;   // 65536
    int n = idx >> 8, k = idx & 255;
    g_w2h[n * 264 + k] = __float2half_rn(W2[k * 256 + n]);
}
__global__ void prep_w1(const float* __restrict__ W1)
{
    int n = blockIdx.x, k = threadIdx.x;        // 256 x 72
    float v = (k < 64) ? W1[k * 256 + n] : 0.0f;
    __half hi = __float2half_rn(v);
    g_w1h[n * 72 + k] = hi;
    g_w1l[n * 72 + k] = __float2half_rn(v - __half2float(hi));
}

// ---------------------------------------------------------------------------
// Kernel 2 (HMMA, persistent, 512 thr, prefetched): A = 30*(xenc@W1[0:64]+b1)
// ---------------------------------------------------------------------------
#define PROW 144              // bytes per [.,72-half] row
#define SMP_WH 0              // 256*144 = 36864
#define SMP_WL 36864
#define SMP_XH 73728          // 64*144 = 9216
#define SMP_XL 82944
#define SMP_TOT 92160

__global__ __launch_bounds__(512, 1) void proj_kernel(
    const float* __restrict__ b1)
{
    extern __shared__ char smem[];
    const uint32_t sb = smem_u32(smem);
    int tid  = threadIdx.x;
    int w    = tid >> 5;
    int lane = tid & 31;

    // Stage W1 hi/lo (resident)
    {
        const float4* s0 = (const float4*)g_w1h;
        const float4* s1 = (const float4*)g_w1l;
        float4* d0 = (float4*)(smem + SMP_WH);
        float4* d1 = (float4*)(smem + SMP_WL);
        for (int i = tid; i < 256 * 144 / 16; i += 512) { d0[i] = s0[i]; d1[i] = s1[i]; }
    }

    const int wm = (w & 3) * 16;       // 4 m-groups x 16 rows
    const int wn = (w >> 2) * 64;      // 4 n-groups x 64 cols

    float b1r[16];
    #pragma unroll
    for (int q = 0; q < 16; q++)
        b1r[q] = b1[wn + (q >> 1) * 8 + (lane & 3) * 2 + (q & 1)];

    const uint32_t a_toff = (uint32_t)(wm + (lane & 15)) * PROW + (uint32_t)(lane >> 4) * 16;
    const uint32_t b_toff = (uint32_t)(wn + (lane & 7) + ((lane >> 4) & 1) * 8) * PROW
                          + (uint32_t)((lane >> 3) & 1) * 16;

    const int lrow = tid >> 3;             // cell row this thread loads (64 rows)
    const int lk   = (tid & 7) * 8;        // 8 k values
    __syncthreads();

    // Prologue prefetch
    float4 v0, v1;
    {
        const float4* src = (const float4*)(g_xenc + ((size_t)blockIdx.x * 64 + lrow) * 64 + lk);
        v0 = src[0]; v1 = src[1];
    }

    for (int tile = blockIdx.x; tile < 9216; tile += 148) {
        size_t cell0 = (size_t)tile * 64;

        // Split held regs -> smem
        {
            float vv[8] = {v0.x, v0.y, v0.z, v0.w, v1.x, v1.y, v1.z, v1.w};
            uint32_t hv[4], lv[4];
            #pragma unroll
            for (int p = 0; p < 4; p++) {
                __half h0 = __float2half_rn(vv[2*p]),   h1 = __float2half_rn(vv[2*p+1]);
                __half l0 = __float2half_rn(vv[2*p]   - __half2float(h0));
                __half l1 = __float2half_rn(vv[2*p+1] - __half2float(h1));
                __half2 ph = __halves2half2(h0, h1), pl = __halves2half2(l0, l1);
                hv[p] = *(uint32_t*)&ph;  lv[p] = *(uint32_t*)&pl;
            }
            *(uint4*)(smem + SMP_XH + lrow * PROW + lk * 2) = make_uint4(hv[0], hv[1], hv[2], hv[3]);
            *(uint4*)(smem + SMP_XL + lrow * PROW + lk * 2) = make_uint4(lv[0], lv[1], lv[2], lv[3]);
        }
        __syncthreads();

        // Prefetch next tile while GEMM runs
        int ntile = tile + 148;
        if (ntile < 9216) {
            const float4* src = (const float4*)(g_xenc + ((size_t)ntile * 64 + lrow) * 64 + lk);
            v0 = src[0]; v1 = src[1];
        }

        float acc[8][4];
        #pragma unroll
        for (int nt = 0; nt < 8; nt++)
            #pragma unroll
            for (int c = 0; c < 4; c++) acc[nt][c] = 0.0f;

        const uint32_t abase[3] = {sb + SMP_XH, sb + SMP_XL, sb + SMP_XH};
        const uint32_t bbase[3] = {sb + SMP_WH, sb + SMP_WH, sb + SMP_WL};
        #pragma unroll
        for (int s = 0; s < 3; s++) {
            uint32_t a_addr = abase[s] + a_toff;
            uint32_t b_addr = bbase[s] + b_toff;
            #pragma unroll
            for (int ks = 0; ks < 4; ks++) {
                uint32_t af[4];
                ldsm_x4(af, a_addr);
                #pragma unroll
                for (int np = 0; np < 4; np++) {
                    uint32_t bf[4];
                    ldsm_x4(bf, b_addr + np * 16 * PROW);
                    mma16816(acc[np * 2 + 0], af, bf + 0);
                    mma16816(acc[np * 2 + 1], af, bf + 2);
                }
                a_addr += 32;
                b_addr += 32;
            }
        }

        // Epilogue: A = 30*(z1 + b1), direct STG.64
        {
            int r0 = wm + (lane >> 2);
            #pragma unroll
            for (int nt = 0; nt < 8; nt++) {
                int n0 = wn + nt * 8 + (lane & 3) * 2;
                float2 o0, o1;
                o0.x = 30.0f * (acc[nt][0] + b1r[nt*2+0]);
                o0.y = 30.0f * (acc[nt][1] + b1r[nt*2+1]);
                o1.x = 30.0f * (acc[nt][2] + b1r[nt*2+0]);
                o1.y = 30.0f * (acc[nt][3] + b1r[nt*2+1]);
                *(float2*)&g_A[(cell0 + r0)     * 256 + n0] = o0;
                *(float2*)&g_A[(cell0 + r0 + 8) * 256 + n0] = o1;
            }
        }
        __syncthreads();
    }
}

// ---------------------------------------------------------------------------
// Kernel 3: persistent HMMA SIREN (256 thr, warp tile 32x64), software-
// pipelined over (tile, half) units with alternating A buffers:
//   unit u: GEMM(buf[u&1]) ; phase1(unit u+1 -> buf[(u+1)&1]) ; epilogue ; sync
// Slots double-buffered by tile parity so output-combine never races.
// ---------------------------------------------------------------------------
#define AROW   528            // bytes per [.,264-half] row
#define SM_B    0             // 256*528 = 135168
#define SM_A0   135168        // 64*528  =  33792
#define SM_A1   168960        // 64*528  =  33792
#define SM_W1T  202752        // 1024
#define SM_SLOT 203776        // 2*512*4 = 4096
#define SM_TOT  207872

struct TP { size_t slice; float tau, ctc; int bq, pix0; };

__device__ __forceinline__ TP make_tp(const float* __restrict__ tcoord, int tile)
{
    TP t;
    t.bq  = tile & 63;
    t.pix0 = (tile >> 6) * 64;
    int b = t.bq >> 5;
    float tc = tcoord[t.bq];
    tc = fminf(fmaxf(tc, -1.0f), 1.0f - 1e-6f);
    const float df = 2.0f / 31.0f;
    int ti = (int)floorf((tc + 1.0f) / df);
    t.tau = (tc - (-1.0f + (float)ti * df)) / df;
    t.ctc = 30.0f * tc;
    t.slice = (size_t)(b * 32 + ti);
    return t;
}

// phase1: h1 = sin(A + ctc*w1t) -> fp16 into buf (this thread: row p1row, k [p1k,p1k+64))
__device__ __forceinline__ void do_phase1(
    char* __restrict__ buf, const float* __restrict__ w1t,
    size_t slice, int pix0, float ctc, int p1row, int p1k)
{
    const float4* s4 = (const float4*)(g_A + (slice * HW + pix0 + p1row) * 256 + p1k);
    char* hb = buf + p1row * AROW + p1k * 2;
    #pragma unroll
    for (int c = 0; c < 2; c++) {
        float4 a4[8];
        #pragma unroll
        for (int j = 0; j < 8; j++) a4[j] = s4[c * 8 + j];   // MLP=8 front-batched
        #pragma unroll
        for (int j = 0; j < 4; j++) {
            float4 a0 = a4[2*j], a1 = a4[2*j+1];
            const float4 w0  = *(const float4*)&w1t[p1k + c*32 + 8*j];
            const float4 w1v = *(const float4*)&w1t[p1k + c*32 + 8*j + 4];
            float s[8];
            s[0] = __sinf(fmaf(ctc, w0.x,  a0.x));
            s[1] = __sinf(fmaf(ctc, w0.y,  a0.y));
            s[2] = __sinf(fmaf(ctc, w0.z,  a0.z));
            s[3] = __sinf(fmaf(ctc, w0.w,  a0.w));
            s[4] = __sinf(fmaf(ctc, w1v.x, a1.x));
            s[5] = __sinf(fmaf(ctc, w1v.y, a1.y));
            s[6] = __sinf(fmaf(ctc, w1v.z, a1.z));
            s[7] = __sinf(fmaf(ctc, w1v.w, a1.w));
            uint32_t hv[4];
            #pragma unroll
            for (int p = 0; p < 4; p++) {
                __half2 ph = __halves2half2(__float2half_rn(s[2*p]),
                                            __float2half_rn(s[2*p+1]));
                hv[p] = *(uint32_t*)&ph;
            }
            *(uint4*)(hb + c * 64 + j * 16) = make_uint4(hv[0], hv[1], hv[2], hv[3]);
        }
    }
}

__device__ __forceinline__ void do_gemm(
    float (&acc)[2][8][4], uint32_t a_base, uint32_t b_base)
{
    #pragma unroll
    for (int mt = 0; mt < 2; mt++)
        #pragma unroll
        for (int nt = 0; nt < 8; nt++)
            #pragma unroll
            for (int c = 0; c < 4; c++) acc[mt][nt][c] = 0.0f;

    uint32_t a_addr = a_base;
    uint32_t b_addr = b_base;
    #pragma unroll 4
    for (int ks = 0; ks < 16; ks++) {
        uint32_t af0[4], af1[4];
        ldsm_x4(af0, a_addr);
        ldsm_x4(af1, a_addr + 16 * AROW);
        #pragma unroll
        for (int np = 0; np < 4; np++) {
            uint32_t bf[4];
            ldsm_x4(bf, b_addr + np * 16 * AROW);
            mma16816(acc[0][np * 2 + 0], af0, bf + 0);
            mma16816(acc[0][np * 2 + 1], af0, bf + 2);
            mma16816(acc[1][np * 2 + 0], af1, bf + 0);
            mma16816(acc[1][np * 2 + 1], af1, bf + 2);
        }
        a_addr += 32;
        b_addr += 32;
    }
}

__device__ __forceinline__ void do_epilogue(
    const float (&acc)[2][8][4], const float (&b2r)[16], const float (&w3r)[16],
    float* __restrict__ slots, int slot_base, int wm, int lane)
{
    float p[2][2];
    #pragma unroll
    for (int mt = 0; mt < 2; mt++)
        #pragma unroll
        for (int rh = 0; rh < 2; rh++) {
            float s = 0.0f;
            #pragma unroll
            for (int nt = 0; nt < 8; nt++) {
                int c0 = rh * 2;
                s = fmaf(__sinf(fmaf(30.0f, acc[mt][nt][c0],     b2r[nt*2+0])), w3r[nt*2+0], s);
                s = fmaf(__sinf(fmaf(30.0f, acc[mt][nt][c0 + 1], b2r[nt*2+1])), w3r[nt*2+1], s);
            }
            p[mt][rh] = s;
        }
    #pragma unroll
    for (int msk = 1; msk < 4; msk <<= 1) {
        #pragma unroll
        for (int mt = 0; mt < 2; mt++)
            #pragma unroll
            for (int rh = 0; rh < 2; rh++)
                p[mt][rh] += __shfl_xor_sync(0xffffffffu, p[mt][rh], msk);
    }
    if ((lane & 3) == 0) {
        #pragma unroll
        for (int mt = 0; mt < 2; mt++)
            #pragma unroll
            for (int rh = 0; rh < 2; rh++)
                slots[slot_base + wm + mt * 16 + rh * 8 + (lane >> 2)] = p[mt][rh];
    }
}

__global__ __launch_bounds__(256, 1) void main_kernel(
    const float* __restrict__ tcoord, const float* __restrict__ W1,
    const float* __restrict__ b2, const float* __restrict__ W3,
    const float* __restrict__ b3, float* __restrict__ out)
{
    extern __shared__ char smem[];
    const uint32_t sb = smem_u32(smem);
    int tid  = threadIdx.x;
    int w    = tid >> 5;
    int lane = tid & 31;

    // Stage W2 fp16 (resident) + w1 last row
    {
        const float4* src = (const float4*)g_w2h;
        float4*       dst = (float4*)(smem + SM_B);
        for (int i = tid; i < 256 * 528 / 16; i += 256) dst[i] = src[i];
    }
    float* w1t   = (float*)(smem + SM_W1T);
    float* slots = (float*)(smem + SM_SLOT);
    if (tid < 256) w1t[tid] = W1[64 * 256 + tid];
    __syncthreads();

    const float b3v = b3[0];

    const int wm = (w & 1) * 32;       // 2 m-groups x 32 rows
    const int wn = (w >> 1) * 64;      // 4 n-groups x 64 cols
    const int ng = w >> 1;

    float b2r[16], w3r[16];
    #pragma unroll
    for (int q = 0; q < 16; q++) {
        int n = wn + (q >> 1) * 8 + (lane & 3) * 2 + (q & 1);
        b2r[q] = 30.0f * b2[n];
        w3r[q] = W3[n];
    }

    const uint32_t a_toff = (uint32_t)(wm + (lane & 15)) * AROW + (uint32_t)(lane >> 4) * 16;
    const uint32_t b_toff = (uint32_t)(wn + (lane & 7) + ((lane >> 4) & 1) * 8) * AROW
                          + (uint32_t)((lane >> 3) & 1) * 16;
    const uint32_t b_base = sb + SM_B + b_toff;
    const uint32_t abuf[2] = {sb + SM_A0 + a_toff, sb + SM_A1 + a_toff};
    char* const   abufp[2] = {smem + SM_A0, smem + SM_A1};

    const int p1row = tid >> 2;          // phase-1 row (64 rows, 4 thr/row)
    const int p1k   = (tid & 3) * 64;    // phase-1 k start (64 values)

    int tile = blockIdx.x;
    TP cur = make_tp(tcoord, tile);

    // Prologue: fill buf0 with (tile0, h=0)
    do_phase1(abufp[0], w1t, cur.slice, cur.pix0, cur.ctc, p1row, p1k);
    __syncthreads();

    int bufp = 0, par = 0;
    float acc[2][8][4];

    while (true) {
        // ---- unit A: GEMM h=0 ; phase1 h=1 -> other buf ; epilogue h=0 ----
        do_gemm(acc, abuf[bufp], b_base);
        do_phase1(abufp[bufp ^ 1], w1t, cur.slice + 1, cur.pix0, cur.ctc, p1row, p1k);
        do_epilogue(acc, b2r, w3r, slots, par * 512 + ng * 64, wm, lane);
        __syncthreads();
        bufp ^= 1;

        // ---- unit B: GEMM h=1 ; phase1 next tile h=0 ; epilogue h=1 ----
        do_gemm(acc, abuf[bufp], b_base);
        int ntile = tile + 148;
        bool more = (ntile < 9216);
        TP nxt;
        if (more) {
            nxt = make_tp(tcoord, ntile);
            do_phase1(abufp[bufp ^ 1], w1t, nxt.slice, nxt.pix0, nxt.ctc, p1row, p1k);
        }
        do_epilogue(acc, b2r, w3r, slots, par * 512 + 256 + ng * 64, wm, lane);
        __syncthreads();
        bufp ^= 1;

        // ---- combine + output (parity-protected against next unit A) ----
        if (tid < 64) {
            int sb0 = par * 512;
            float zf = slots[sb0 + tid]       + slots[sb0 + 64 + tid]
                     + slots[sb0 + 128 + tid] + slots[sb0 + 192 + tid];
            float zc = slots[sb0 + 256 + tid] + slots[sb0 + 320 + tid]
                     + slots[sb0 + 384 + tid] + slots[sb0 + 448 + tid];
            out[(size_t)cur.bq * HW + cur.pix0 + tid] = fmaf(cur.tau, zc - zf, zf) + b3v;
        }

        if (!more) break;
        cur = nxt;
        tile = ntile;
        par ^= 1;
    }
}

// ---------------------------------------------------------------------------
extern "C" void kernel_launch(void* const* d_in, const int* in_sizes, int n_in,
                              void* d_out, int out_size)
{
    const float* x_real  = (const float*)d_in[0];
    const float* x_imag  = (const float*)d_in[1];
    const float* t_coord = (const float*)d_in[2];
    const float* enc_w   = (const float*)d_in[3];
    const float* enc_b   = (const float*)d_in[4];
    const float* W1      = (const float*)d_in[5];
    const float* b1      = (const float*)d_in[6];
    const float* W2      = (const float*)d_in[7];
    const float* b2      = (const float*)d_in[8];
    const float* W3      = (const float*)d_in[9];
    const float* b3      = (const float*)d_in[10];
    float*       out     = (float*)d_out;

    size_t smem1 = (3456 + 64 + 256 * 65) * sizeof(float);
    cudaFuncSetAttribute(conv_kernel, cudaFuncAttributeMaxDynamicSharedMemorySize, (int)smem1);
    cudaFuncSetAttribute(proj_kernel, cudaFuncAttributeMaxDynamicSharedMemorySize, SMP_TOT);
    cudaFuncSetAttribute(main_kernel, cudaFuncAttributeMaxDynamicSharedMemorySize, SM_TOT);

    prep_w2<<<256, 256>>>(W2);
    prep_w1<<<256, 72>>>(W1);
    conv_kernel<<<2304, 256, smem1>>>(x_real, x_imag, enc_w, enc_b);
    proj_kernel<<<148, 512, SMP_TOT>>>(b1);
    main_kernel<<<148, 256, SM_TOT>>>(t_coord, W1, b2, W3, b3, out);
}